// round 13
// baseline (speedup 1.0000x reference)
#include <cuda_runtime.h>
#include <cuda_bf16.h>

#define EPS   1e-6f
#define LN2   0.6931471805599453f
#define RROWS 51   // 255 = 5 * 51
#define OUTW  62   // output cols per warp (warps overlap by one pixel pair)

__device__ __forceinline__ float fast_rcp(float a) {
    float r;
    asm("rcp.approx.f32 %0, %1;" : "=f"(r) : "f"(a));
    return r;
}

__device__ __forceinline__ void row_h(float2 v,
                                      float& hv0, float& hl0,
                                      float& hv1, float& hl1)
{
    float l0 = v.x * __log2f(v.x + EPS);
    float l1 = v.y * __log2f(v.y + EPS);
    float vn = __shfl_down_sync(0xffffffffu, v.x, 1);
    float ln = __shfl_down_sync(0xffffffffu, l0, 1);
    hv0 = v.x + v.y;  hl0 = l0 + l1;
    hv1 = v.y + vn;   hl1 = l1 + ln;
}

__device__ __forceinline__ void emit(float hv0p, float hl0p, float hv1p, float hl1p,
                                     float hv0, float hl0, float hv1, float hl1,
                                     float* po, bool ok0, bool ok1)
{
    float s0  = hv0p + hv0;
    float sl0 = hl0p + hl0;
    float S0  = s0 + EPS;
    float e0  = fmaf(s0, __log2f(S0), -sl0) * fast_rcp(S0) * LN2;
    float s1  = hv1p + hv1;
    float sl1 = hl1p + hl1;
    float S1  = s1 + EPS;
    float e1  = fmaf(s1, __log2f(S1), -sl1) * fast_rcp(S1) * LN2;
    if (ok0) __stcs(po,     e0);
    if (ok1) __stcs(po + 1, e1);
}

__global__ __launch_bounds__(160)
void entropy2x2_k8(const float* __restrict__ x, float* __restrict__ out)
{
    const int lane  = threadIdx.x & 31;
    const int warp  = threadIdx.x >> 5;        // 0..4
    const int plane = blockIdx.z;              // 0..511
    const int pc    = warp * OUTW + lane * 2;  // 0..310
    const int lc    = min(pc, 254);            // in-bounds, 8B-aligned load col
    const int yBase = blockIdx.y * RROWS;      // 0,51,102,153,204

    const float* __restrict__ p  = x   + (size_t)plane * (256 * 256)
                                       + (size_t)yBase * 256 + lc;
    float*       __restrict__ po = out + (size_t)plane * (255 * 255)
                                       + (size_t)yBase * 255 + pc;

    const bool act = (lane < 31);              // lane31 only feeds shfl
    const bool ok0 = act && (pc     < 255);
    const bool ok1 = act && (pc + 1 < 255);

    // ---- prime: row yBase + two rows in flight (prefetch depth 2) ----
    float2 v  = *reinterpret_cast<const float2*>(p);       p += 256; // row y
    float2 va = *reinterpret_cast<const float2*>(p);       p += 256; // row y+1
    float2 vb = *reinterpret_cast<const float2*>(p);       p += 256; // row y+2

    float hv0_p, hl0_p, hv1_p, hl1_p;
    row_h(v, hv0_p, hl0_p, hv1_p, hl1_p);

    // ---- main loop: 49 iterations (windows 0..48), 2 loads in flight ----
    #pragma unroll 7
    for (int r = 0; r < RROWS - 2; r++) {
        float2 vc = va;
        va = vb;
        vb = *reinterpret_cast<const float2*>(p);          p += 256; // row y+3+r

        float hv0, hl0, hv1, hl1;
        row_h(vc, hv0, hl0, hv1, hl1);
        emit(hv0_p, hl0_p, hv1_p, hl1_p, hv0, hl0, hv1, hl1, po, ok0, ok1);

        hv0_p = hv0; hl0_p = hl0; hv1_p = hv1; hl1_p = hl1;
        po += 255;
    }

    // ---- peeled windows 49, 50: consume va, vb; no further loads ----
    {
        float hv0, hl0, hv1, hl1;
        row_h(va, hv0, hl0, hv1, hl1);
        emit(hv0_p, hl0_p, hv1_p, hl1_p, hv0, hl0, hv1, hl1, po, ok0, ok1);
        hv0_p = hv0; hl0_p = hl0; hv1_p = hv1; hl1_p = hl1;
        po += 255;
    }
    {
        float hv0, hl0, hv1, hl1;
        row_h(vb, hv0, hl0, hv1, hl1);
        emit(hv0_p, hl0_p, hv1_p, hl1_p, hv0, hl0, hv1, hl1, po, ok0, ok1);
    }
}

extern "C" void kernel_launch(void* const* d_in, const int* in_sizes, int n_in,
                              void* d_out, int out_size)
{
    const float* x = (const float*)d_in[0];
    float* out = (float*)d_out;

    // 5 warps x 62 output cols = 310 >= 255; 5 row-strips of 51 cover 255 rows.
    dim3 block(160);
    dim3 grid(1, 5, 512);
    entropy2x2_k8<<<grid, block>>>(x, out);
}

// round 14
// speedup vs baseline: 1.1322x; 1.1322x over previous
#include <cuda_runtime.h>
#include <cuda_bf16.h>

#define EPS   1e-6f
#define LN2   0.6931471805599453f
#define RROWS 85   // 255 = 3 * 85 -> 512*3 = 1536 CTAs = single wave on 148 SMs
#define OUTW  62   // output cols per warp (warps overlap by one pixel pair)

__device__ __forceinline__ float fast_rcp(float a) {
    float r;
    asm("rcp.approx.f32 %0, %1;" : "=f"(r) : "f"(a));
    return r;
}

// From a pixel pair (cols pc, pc+1) build horizontal sums for windows at
// pc (in-register) and pc+1 (right neighbor via shfl; lane31 result unused).
__device__ __forceinline__ void row_h(float2 v,
                                      float& hv0, float& hl0,
                                      float& hv1, float& hl1)
{
    float l0 = v.x * __log2f(v.x + EPS);
    float l1 = v.y * __log2f(v.y + EPS);
    float vn = __shfl_down_sync(0xffffffffu, v.x, 1);
    float ln = __shfl_down_sync(0xffffffffu, l0, 1);
    hv0 = v.x + v.y;  hl0 = l0 + l1;
    hv1 = v.y + vn;   hl1 = l1 + ln;
}

__device__ __forceinline__ void emit(float hv0p, float hl0p, float hv1p, float hl1p,
                                     float hv0, float hl0, float hv1, float hl1,
                                     float* po, bool ok0, bool ok1)
{
    float s0  = hv0p + hv0;
    float sl0 = hl0p + hl0;
    float S0  = s0 + EPS;
    float e0  = fmaf(s0, __log2f(S0), -sl0) * fast_rcp(S0) * LN2;
    float s1  = hv1p + hv1;
    float sl1 = hl1p + hl1;
    float S1  = s1 + EPS;
    float e1  = fmaf(s1, __log2f(S1), -sl1) * fast_rcp(S1) * LN2;
    if (ok0) __stcs(po,     e0);
    if (ok1) __stcs(po + 1, e1);
}

__global__ __launch_bounds__(160)
void entropy2x2_k9(const float* __restrict__ x, float* __restrict__ out)
{
    const int lane  = threadIdx.x & 31;
    const int warp  = threadIdx.x >> 5;        // 0..4
    const int plane = blockIdx.z;              // 0..511
    const int pc    = warp * OUTW + lane * 2;  // 0..310 (inactive tail clamped)
    const int lc    = min(pc, 254);            // in-bounds, 8B-aligned load col
    const int yBase = blockIdx.y * RROWS;      // 0, 85, 170

    const float* __restrict__ p  = x   + (size_t)plane * (256 * 256)
                                       + (size_t)yBase * 256 + lc;
    float*       __restrict__ po = out + (size_t)plane * (255 * 255)
                                       + (size_t)yBase * 255 + pc;

    const bool act = (lane < 31);              // lane31 only feeds shfl
    const bool ok0 = act && (pc     < 255);
    const bool ok1 = act && (pc + 1 < 255);

    // ---- prime row yBase, prefetch row yBase+1 (depth-1, k7-proven) ----
    float2 v  = *reinterpret_cast<const float2*>(p);       p += 256;
    float2 vp = *reinterpret_cast<const float2*>(p);       p += 256;  // in flight

    float hv0_p, hl0_p, hv1_p, hl1_p;
    row_h(v, hv0_p, hl0_p, hv1_p, hl1_p);

    // ---- main loop: 84 iterations = 4 * 21, uniform, branch-free ----
    #pragma unroll 4
    for (int r = 0; r < RROWS - 1; r++) {
        float2 vc = vp;
        vp = *reinterpret_cast<const float2*>(p);          p += 256;  // prefetch r+2

        float hv0, hl0, hv1, hl1;
        row_h(vc, hv0, hl0, hv1, hl1);
        emit(hv0_p, hl0_p, hv1_p, hl1_p, hv0, hl0, hv1, hl1, po, ok0, ok1);

        hv0_p = hv0; hl0_p = hl0; hv1_p = hv1; hl1_p = hl1;
        po += 255;
    }

    // ---- peeled last row: consume final prefetch, no further load ----
    {
        float hv0, hl0, hv1, hl1;
        row_h(vp, hv0, hl0, hv1, hl1);
        emit(hv0_p, hl0_p, hv1_p, hl1_p, hv0, hl0, hv1, hl1, po, ok0, ok1);
    }
}

extern "C" void kernel_launch(void* const* d_in, const int* in_sizes, int n_in,
                              void* d_out, int out_size)
{
    const float* x = (const float*)d_in[0];
    float* out = (float*)d_out;

    // 5 warps x 62 output cols = 310 >= 255; 3 row-strips of 85 cover 255 rows.
    // 512 planes x 3 strips = 1536 CTAs -> one wave at 160 thr/CTA on 148 SMs.
    dim3 block(160);
    dim3 grid(1, 3, 512);
    entropy2x2_k9<<<grid, block>>>(x, out);
}